// round 3
// baseline (speedup 1.0000x reference)
#include <cuda_runtime.h>
#include <cuda_bf16.h>

// Shapes
#define Bb 4
#define Ll 48
#define LP 96
#define Nn 512
#define Dd 128
#define DF 512
#define Hh 8
#define HD 16

#define M1 (Bb*Ll*Nn)    // 98304
#define M2 (Bb*LP*Nn)    // 196608
#define BLn (Bb*Ll)      // 192

// ---------------- scratch (static device memory; no allocations) ----------------
__device__ float g_q [M1*Dd];
__device__ float g_k [M2*Dd];
__device__ float g_v [M2*Dd];
__device__ float g_t [M1*Dd];
__device__ float g_h [M1*Dd];
__device__ float g_xn[M1*Dd];
__device__ float g_y [M1*Dd];
__device__ float g_big[(long long)M1*DF];          // y1 then A
__device__ float g_Hb[(long long)BLn*640*Nn];      // Hc: [192][640][512]
__device__ float g_go[(long long)BLn*Dd*Nn];       // gout: [192][128][512]

__device__ __forceinline__ unsigned f2tf32(float x) {
    unsigned u;
    asm("cvt.rna.tf32.f32 %0, %1;" : "=r"(u) : "f"(x));
    return u;
}

// ---------------- MMA compute phase on one smem buffer ----------------
__device__ __forceinline__ void mma_tile(
    const float (*__restrict__ As)[20], const float (*__restrict__ Bs)[136],
    int wm, int wn, int lr, int lc, float acc[4][4][4])
{
    #pragma unroll
    for (int kk = 0; kk < 16; kk += 8) {
        unsigned a[4][4], b[4][2];
        #pragma unroll
        for (int mf = 0; mf < 4; mf++) {
            int row = wm*64 + mf*16 + lr;
            a[mf][0] = __float_as_uint(As[row  ][kk + lc]);
            a[mf][1] = __float_as_uint(As[row+8][kk + lc]);
            a[mf][2] = __float_as_uint(As[row  ][kk + lc + 4]);
            a[mf][3] = __float_as_uint(As[row+8][kk + lc + 4]);
        }
        #pragma unroll
        for (int nf = 0; nf < 4; nf++) {
            int col = wn*32 + nf*8 + lr;
            b[nf][0] = __float_as_uint(Bs[kk + lc    ][col]);
            b[nf][1] = __float_as_uint(Bs[kk + lc + 4][col]);
        }
        #pragma unroll
        for (int mf = 0; mf < 4; mf++)
            #pragma unroll
            for (int nf = 0; nf < 4; nf++) {
                asm volatile(
                    "mma.sync.aligned.m16n8k8.row.col.f32.tf32.tf32.f32 "
                    "{%0,%1,%2,%3}, {%4,%5,%6,%7}, {%8,%9}, {%0,%1,%2,%3};\n"
                    : "+f"(acc[mf][nf][0]), "+f"(acc[mf][nf][1]),
                      "+f"(acc[mf][nf][2]), "+f"(acc[mf][nf][3])
                    : "r"(a[mf][0]), "r"(a[mf][1]), "r"(a[mf][2]), "r"(a[mf][3]),
                      "r"(b[nf][0]), "r"(b[nf][1]));
            }
    }
}

// ---------------- TF32 tensor-core GEMM, double-buffered: C = A@B (+bias)(+relu) ----------------
// A[M,K] row-major, B[K,N] row-major, C[M,N]. 128x128 tile, k-step 16, 8 warps.
// Per batch z: A += (modA? z%modA : z)*sA ; B += z*sB ; C += z*sC.
__global__ void __launch_bounds__(256) sgemm_kernel(
    const float* __restrict__ A, const float* __restrict__ B, float* __restrict__ C,
    int M, int N, int K,
    long long sA, long long sB, long long sC, int modA,
    const float* __restrict__ bias, int doRelu)
{
    __shared__ float As[2][128][20];
    __shared__ float Bs[2][16][136];

    int z = blockIdx.z;
    const float* Ap = A + (long long)(modA > 0 ? (z % modA) : z) * sA;
    const float* Bp = B + (long long)z * sB;
    float*       Cp = C + (long long)z * sC;

    int tid  = threadIdx.x;
    int warp = tid >> 5;
    int lane = tid & 31;
    int wm = warp >> 2;   // 0..1
    int wn = warp & 3;    // 0..3
    int lr = lane >> 2;   // 0..7
    int lc = lane & 3;    // 0..3

    int brow = blockIdx.y * 128;
    int bcol = blockIdx.x * 128;

    // load maps
    int rA = tid >> 2;           // 0..63  (second load at +64)
    int cA = (tid & 3) * 4;      // 0,4,8,12
    int rB = tid >> 5;           // 0..7   (second load at +8)
    int cB = (tid & 31) * 4;     // 0..124

    const float* aPtr = Ap + (long long)(brow + rA) * K + cA;
    const float* bPtr = Bp + (long long)rB * N + bcol + cB;
    const long long aOff2 = 64LL * K;
    const long long bOff2 = 8LL * N;

    float acc[4][4][4];
    #pragma unroll
    for (int i = 0; i < 4; i++)
        #pragma unroll
        for (int j = 0; j < 4; j++)
            #pragma unroll
            for (int r = 0; r < 4; r++) acc[i][j][r] = 0.f;

    // prologue: tile 0 -> buf 0
    float4 va0 = *(const float4*)aPtr;
    float4 va1 = *(const float4*)(aPtr + aOff2);
    float4 vb0 = *(const float4*)bPtr;
    float4 vb1 = *(const float4*)(bPtr + bOff2);
    aPtr += 16; bPtr += 16LL * N;

    {
        As[0][rA   ][cA+0] = __uint_as_float(f2tf32(va0.x));
        As[0][rA   ][cA+1] = __uint_as_float(f2tf32(va0.y));
        As[0][rA   ][cA+2] = __uint_as_float(f2tf32(va0.z));
        As[0][rA   ][cA+3] = __uint_as_float(f2tf32(va0.w));
        As[0][rA+64][cA+0] = __uint_as_float(f2tf32(va1.x));
        As[0][rA+64][cA+1] = __uint_as_float(f2tf32(va1.y));
        As[0][rA+64][cA+2] = __uint_as_float(f2tf32(va1.z));
        As[0][rA+64][cA+3] = __uint_as_float(f2tf32(va1.w));
        Bs[0][rB  ][cB+0] = __uint_as_float(f2tf32(vb0.x));
        Bs[0][rB  ][cB+1] = __uint_as_float(f2tf32(vb0.y));
        Bs[0][rB  ][cB+2] = __uint_as_float(f2tf32(vb0.z));
        Bs[0][rB  ][cB+3] = __uint_as_float(f2tf32(vb0.w));
        Bs[0][rB+8][cB+0] = __uint_as_float(f2tf32(vb1.x));
        Bs[0][rB+8][cB+1] = __uint_as_float(f2tf32(vb1.y));
        Bs[0][rB+8][cB+2] = __uint_as_float(f2tf32(vb1.z));
        Bs[0][rB+8][cB+3] = __uint_as_float(f2tf32(vb1.w));
    }
    __syncthreads();

    int buf = 0;
    for (int k0 = 16; k0 < K; k0 += 16) {
        // issue next tile's loads early
        va0 = *(const float4*)aPtr;
        va1 = *(const float4*)(aPtr + aOff2);
        vb0 = *(const float4*)bPtr;
        vb1 = *(const float4*)(bPtr + bOff2);
        aPtr += 16; bPtr += 16LL * N;

        // compute current buffer while loads are in flight
        mma_tile(As[buf], Bs[buf], wm, wn, lr, lc, acc);

        // store into alternate buffer
        int nb = buf ^ 1;
        As[nb][rA   ][cA+0] = __uint_as_float(f2tf32(va0.x));
        As[nb][rA   ][cA+1] = __uint_as_float(f2tf32(va0.y));
        As[nb][rA   ][cA+2] = __uint_as_float(f2tf32(va0.z));
        As[nb][rA   ][cA+3] = __uint_as_float(f2tf32(va0.w));
        As[nb][rA+64][cA+0] = __uint_as_float(f2tf32(va1.x));
        As[nb][rA+64][cA+1] = __uint_as_float(f2tf32(va1.y));
        As[nb][rA+64][cA+2] = __uint_as_float(f2tf32(va1.z));
        As[nb][rA+64][cA+3] = __uint_as_float(f2tf32(va1.w));
        Bs[nb][rB  ][cB+0] = __uint_as_float(f2tf32(vb0.x));
        Bs[nb][rB  ][cB+1] = __uint_as_float(f2tf32(vb0.y));
        Bs[nb][rB  ][cB+2] = __uint_as_float(f2tf32(vb0.z));
        Bs[nb][rB  ][cB+3] = __uint_as_float(f2tf32(vb0.w));
        Bs[nb][rB+8][cB+0] = __uint_as_float(f2tf32(vb1.x));
        Bs[nb][rB+8][cB+1] = __uint_as_float(f2tf32(vb1.y));
        Bs[nb][rB+8][cB+2] = __uint_as_float(f2tf32(vb1.z));
        Bs[nb][rB+8][cB+3] = __uint_as_float(f2tf32(vb1.w));
        __syncthreads();
        buf = nb;
    }
    mma_tile(As[buf], Bs[buf], wm, wn, lr, lc, acc);

    // epilogue
    #pragma unroll
    for (int mf = 0; mf < 4; mf++) {
        int row0 = brow + wm*64 + mf*16 + lr;
        #pragma unroll
        for (int nf = 0; nf < 4; nf++) {
            int col = bcol + wn*32 + nf*8 + lc*2;
            float bx = 0.f, by = 0.f;
            if (bias) { bx = bias[col]; by = bias[col+1]; }
            float v0 = acc[mf][nf][0] + bx;
            float v1 = acc[mf][nf][1] + by;
            float v2 = acc[mf][nf][2] + bx;
            float v3 = acc[mf][nf][3] + by;
            if (doRelu) {
                v0 = fmaxf(v0, 0.f); v1 = fmaxf(v1, 0.f);
                v2 = fmaxf(v2, 0.f); v3 = fmaxf(v3, 0.f);
            }
            *(float2*)(Cp + (long long)row0*N + col)     = make_float2(v0, v1);
            *(float2*)(Cp + (long long)(row0+8)*N + col) = make_float2(v2, v3);
        }
    }
}

// ---------------- attention: one block per (b, n, h), 256 threads ----------------
// Q [B,Lq,N,D], K/V [B,Lk,N,D]; head h = cols h*16..h*16+15. Softmax over Lk.
// Scores stored transposed St[m][l] (pad 52) so the AV phase is float4-coalesced.
#define STP 52
__global__ void __launch_bounds__(256) attn_kernel(
    const float* __restrict__ Q, const float* __restrict__ Kt, const float* __restrict__ V,
    float* __restrict__ O, int Lq, int Lk)
{
    __shared__ float Qs[48*20];
    __shared__ float Ks[96*20];
    __shared__ float Vs[96*20];
    __shared__ float St[96*STP];   // [m][l]

    int bid = blockIdx.x;
    int h = bid & 7;
    int n = (bid >> 3) & (Nn - 1);
    int b = bid >> 12;
    int tid = threadIdx.x;

    for (int i = tid; i < Lq*4; i += 256) {
        int l = i >> 2, j4 = i & 3;
        float4 v = *(const float4*)(Q + (((long long)(b*Lq + l))*Nn + n)*Dd + h*HD + j4*4);
        *(float4*)&Qs[l*20 + j4*4] = v;
    }
    for (int i = tid; i < Lk*4; i += 256) {
        int m = i >> 2, j4 = i & 3;
        long long base = (((long long)(b*Lk + m))*Nn + n)*Dd + h*HD + j4*4;
        *(float4*)&Ks[m*20 + j4*4] = *(const float4*)(Kt + base);
        *(float4*)&Vs[m*20 + j4*4] = *(const float4*)(V + base);
    }
    __syncthreads();

    const float scale = 0.25f;  // 1/sqrt(16)

    // QK^T with 2l x 4m register tiling; write transposed scores
    int tlc = Lq >> 1;   // 24
    int tmc = Lk >> 2;   // 12 or 24
    for (int t = tid; t < tlc*tmc; t += 256) {
        int tl = t / tmc, tm = t - tl*tmc;
        int l0 = tl*2, m0 = tm*4;
        const float4* q0 = (const float4*)&Qs[l0*20];
        const float4* q1 = (const float4*)&Qs[(l0+1)*20];
        float4 qa0 = q0[0], qa1 = q0[1], qa2 = q0[2], qa3 = q0[3];
        float4 qb0 = q1[0], qb1 = q1[1], qb2 = q1[2], qb3 = q1[3];
        #pragma unroll
        for (int mi = 0; mi < 4; mi++) {
            const float4* kp = (const float4*)&Ks[(m0+mi)*20];
            float4 k0 = kp[0], k1 = kp[1], k2 = kp[2], k3 = kp[3];
            float sA = 0.f, sB = 0.f;
            sA = fmaf(qa0.x,k0.x,sA); sA = fmaf(qa0.y,k0.y,sA); sA = fmaf(qa0.z,k0.z,sA); sA = fmaf(qa0.w,k0.w,sA);
            sA = fmaf(qa1.x,k1.x,sA); sA = fmaf(qa1.y,k1.y,sA); sA = fmaf(qa1.z,k1.z,sA); sA = fmaf(qa1.w,k1.w,sA);
            sA = fmaf(qa2.x,k2.x,sA); sA = fmaf(qa2.y,k2.y,sA); sA = fmaf(qa2.z,k2.z,sA); sA = fmaf(qa2.w,k2.w,sA);
            sA = fmaf(qa3.x,k3.x,sA); sA = fmaf(qa3.y,k3.y,sA); sA = fmaf(qa3.z,k3.z,sA); sA = fmaf(qa3.w,k3.w,sA);
            sB = fmaf(qb0.x,k0.x,sB); sB = fmaf(qb0.y,k0.y,sB); sB = fmaf(qb0.z,k0.z,sB); sB = fmaf(qb0.w,k0.w,sB);
            sB = fmaf(qb1.x,k1.x,sB); sB = fmaf(qb1.y,k1.y,sB); sB = fmaf(qb1.z,k1.z,sB); sB = fmaf(qb1.w,k1.w,sB);
            sB = fmaf(qb2.x,k2.x,sB); sB = fmaf(qb2.y,k2.y,sB); sB = fmaf(qb2.z,k2.z,sB); sB = fmaf(qb2.w,k2.w,sB);
            sB = fmaf(qb3.x,k3.x,sB); sB = fmaf(qb3.y,k3.y,sB); sB = fmaf(qb3.z,k3.z,sB); sB = fmaf(qb3.w,k3.w,sB);
            St[(m0+mi)*STP + l0]     = sA * scale;
            St[(m0+mi)*STP + l0 + 1] = sB * scale;
        }
    }
    __syncthreads();

    // softmax over m (columns of St) — one thread per l
    if (tid < Lq) {
        float mx = -1e30f;
        for (int m = 0; m < Lk; m++) mx = fmaxf(mx, St[m*STP + tid]);
        float sum = 0.f;
        for (int m = 0; m < Lk; m++) {
            float e = __expf(St[m*STP + tid] - mx);
            St[m*STP + tid] = e;
            sum += e;
        }
        float inv = 1.f / sum;
        for (int m = 0; m < Lk; m++) St[m*STP + tid] *= inv;
    }
    __syncthreads();

    // AV: 4l x j4 tiling — V rows reused across 4 l's; all loads float4
    if (tid < (Lq >> 2) * 4) {
        int lt = tid >> 2, j4 = tid & 3;
        int l0 = lt * 4;
        float4 a0 = make_float4(0,0,0,0), a1 = a0, a2 = a0, a3 = a0;
        #pragma unroll 2
        for (int m = 0; m < Lk; m++) {
            float4 v = *(const float4*)&Vs[m*20 + j4*4];
            float4 s = *(const float4*)&St[m*STP + l0];
            a0.x = fmaf(s.x, v.x, a0.x); a0.y = fmaf(s.x, v.y, a0.y);
            a0.z = fmaf(s.x, v.z, a0.z); a0.w = fmaf(s.x, v.w, a0.w);
            a1.x = fmaf(s.y, v.x, a1.x); a1.y = fmaf(s.y, v.y, a1.y);
            a1.z = fmaf(s.y, v.z, a1.z); a1.w = fmaf(s.y, v.w, a1.w);
            a2.x = fmaf(s.z, v.x, a2.x); a2.y = fmaf(s.z, v.y, a2.y);
            a2.z = fmaf(s.z, v.z, a2.z); a2.w = fmaf(s.z, v.w, a2.w);
            a3.x = fmaf(s.w, v.x, a3.x); a3.y = fmaf(s.w, v.y, a3.y);
            a3.z = fmaf(s.w, v.z, a3.z); a3.w = fmaf(s.w, v.w, a3.w);
        }
        long long ob = (((long long)(b*Lq + l0))*Nn + n)*Dd + h*HD + j4*4;
        const long long rs = (long long)Nn * Dd;
        *(float4*)(O + ob)        = a0;
        *(float4*)(O + ob + rs)   = a1;
        *(float4*)(O + ob + 2*rs) = a2;
        *(float4*)(O + ob + 3*rs) = a3;
    }
}

// ---------------- fused residual add + LayerNorm (1 warp per 128-elem row) ----------------
__global__ void __launch_bounds__(256) ln_add_kernel(
    float* __restrict__ out, const float* __restrict__ X, const float* __restrict__ P,
    const float* __restrict__ g, const float* __restrict__ bta, int rows)
{
    int row  = (blockIdx.x * 256 + threadIdx.x) >> 5;
    int lane = threadIdx.x & 31;
    if (row >= rows) return;
    long long base = (long long)row * Dd + lane*4;
    float4 a = *(const float4*)(X + base);
    float4 p = *(const float4*)(P + base);
    float v0 = a.x+p.x, v1 = a.y+p.y, v2 = a.z+p.z, v3 = a.w+p.w;
    float s  = v0+v1+v2+v3;
    float s2 = v0*v0+v1*v1+v2*v2+v3*v3;
    #pragma unroll
    for (int o = 16; o; o >>= 1) {
        s  += __shfl_xor_sync(0xffffffffu, s,  o);
        s2 += __shfl_xor_sync(0xffffffffu, s2, o);
    }
    float mu  = s * (1.f/128.f);
    float var = s2 * (1.f/128.f) - mu*mu;
    float rs  = rsqrtf(var + 1e-5f);
    float4 gg = *(const float4*)(g   + lane*4);
    float4 bb = *(const float4*)(bta + lane*4);
    float4 o4;
    o4.x = (v0-mu)*rs*gg.x + bb.x;
    o4.y = (v1-mu)*rs*gg.y + bb.y;
    o4.z = (v2-mu)*rs*gg.z + bb.z;
    o4.w = (v3-mu)*rs*gg.w + bb.w;
    *(float4*)(out + base) = o4;
}

// ---------------- transpose data[b,l] ([512,128]) -> g0 rows of Hc ([128,512]) ----------------
__global__ void transpose_g0_kernel(const float* __restrict__ in, float* __restrict__ out)
{
    __shared__ float t[32][33];
    int bl = blockIdx.z;
    int n0 = blockIdx.x * 32;
    int c0 = blockIdx.y * 32;
    const float* ip = in  + (long long)bl * (Nn*Dd);
    float*       op = out + (long long)bl * (640*Nn);
    #pragma unroll
    for (int j = 0; j < 32; j += 8)
        t[threadIdx.y + j][threadIdx.x] = ip[(n0 + threadIdx.y + j)*Dd + c0 + threadIdx.x];
    __syncthreads();
    #pragma unroll
    for (int j = 0; j < 32; j += 8)
        op[(c0 + threadIdx.y + j)*Nn + n0 + threadIdx.x] = t[threadIdx.x][threadIdx.y + j];
}

// ---------------- transpose gout[bl] ([128,512]) + gcn_b -> dts ([512,128]) ----------------
__global__ void transpose_gout_kernel(const float* __restrict__ in, const float* __restrict__ gb,
                                      float* __restrict__ out)
{
    __shared__ float t[32][33];
    int bl = blockIdx.z;
    int l  = bl % Ll;
    int n0 = blockIdx.x * 32;
    int o0 = blockIdx.y * 32;
    const float* ip = in  + (long long)bl * (Dd*Nn);
    float*       op = out + (long long)bl * (Nn*Dd);
    #pragma unroll
    for (int j = 0; j < 32; j += 8)
        t[threadIdx.y + j][threadIdx.x] = ip[(o0 + threadIdx.y + j)*Nn + n0 + threadIdx.x];
    __syncthreads();
    #pragma unroll
    for (int j = 0; j < 32; j += 8) {
        int o = o0 + threadIdx.x;
        op[(n0 + threadIdx.y + j)*Dd + o] = t[threadIdx.x][threadIdx.y + j] + gb[l*Dd + o];
    }
}

// ---------------- host ----------------
static inline void gemm(const float* A, const float* B, float* C, int M, int N, int K,
                        long long sA, long long sB, long long sC, int batch, int modA,
                        const float* bias, int relu)
{
    dim3 grid(N/128, M/128, batch);
    sgemm_kernel<<<grid, 256>>>(A, B, C, M, N, K, sA, sB, sC, modA, bias, relu);
}

extern "C" void kernel_launch(void* const* d_in, const int* in_sizes, int n_in,
                              void* d_out, int out_size)
{
    const float* x       = (const float*)d_in[0];
    const float* memory  = (const float*)d_in[1];
    const float* data    = (const float*)d_in[2];
    const float* support = (const float*)d_in[3];
    const float* Wq_s = (const float*)d_in[4];
    const float* Wk_s = (const float*)d_in[5];
    const float* Wv_s = (const float*)d_in[6];
    const float* Wo_s = (const float*)d_in[7];
    const float* Wq_c = (const float*)d_in[8];
    const float* Wk_c = (const float*)d_in[9];
    const float* Wv_c = (const float*)d_in[10];
    const float* Wo_c = (const float*)d_in[11];
    const float* W1   = (const float*)d_in[12];
    const float* b1   = (const float*)d_in[13];
    const float* W2   = (const float*)d_in[14];
    const float* b2   = (const float*)d_in[15];
    const float* W3   = (const float*)d_in[16];
    const float* b3   = (const float*)d_in[17];
    const float* gcnW = (const float*)d_in[18];
    const float* gcnB = (const float*)d_in[19];
    const float* ln1g = (const float*)d_in[20];
    const float* ln1b = (const float*)d_in[21];
    const float* ln2g = (const float*)d_in[22];
    const float* ln2b = (const float*)d_in[23];
    const float* ln3g = (const float*)d_in[24];
    const float* ln3b = (const float*)d_in[25];

    float *q, *k, *v, *t, *h, *xn, *y, *big, *Hb, *go;
    cudaGetSymbolAddress((void**)&q,  g_q);
    cudaGetSymbolAddress((void**)&k,  g_k);
    cudaGetSymbolAddress((void**)&v,  g_v);
    cudaGetSymbolAddress((void**)&t,  g_t);
    cudaGetSymbolAddress((void**)&h,  g_h);
    cudaGetSymbolAddress((void**)&xn, g_xn);
    cudaGetSymbolAddress((void**)&y,  g_y);
    cudaGetSymbolAddress((void**)&big, g_big);
    cudaGetSymbolAddress((void**)&Hb, g_Hb);
    cudaGetSymbolAddress((void**)&go, g_go);

    float* out1 = (float*)d_out;               // LN3(xn + y)
    float* out2 = out1 + (long long)M1 * Dd;   // dts

    const int nLnBlocks = M1 / 8;              // 8 rows per 256-thr block

    // ---- self-attention ----
    gemm(x, Wq_s, q, M1, Dd, Dd, 0,0,0, 1,0, nullptr, 0);
    gemm(x, Wk_s, k, M1, Dd, Dd, 0,0,0, 1,0, nullptr, 0);
    gemm(x, Wv_s, v, M1, Dd, Dd, 0,0,0, 1,0, nullptr, 0);
    attn_kernel<<<Bb*Nn*Hh, 256>>>(q, k, v, t, Ll, Ll);
    gemm(t, Wo_s, q, M1, Dd, Dd, 0,0,0, 1,0, nullptr, 0);
    ln_add_kernel<<<nLnBlocks, 256>>>(h, x, q, ln1g, ln1b, M1);

    // ---- cross-attention ----
    gemm(h,      Wq_c, t, M1, Dd, Dd, 0,0,0, 1,0, nullptr, 0);
    gemm(memory, Wk_c, k, M2, Dd, Dd, 0,0,0, 1,0, nullptr, 0);
    gemm(memory, Wv_c, v, M2, Dd, Dd, 0,0,0, 1,0, nullptr, 0);
    attn_kernel<<<Bb*Nn*Hh, 256>>>(t, k, v, q, Ll, LP);
    gemm(q, Wo_c, t, M1, Dd, Dd, 0,0,0, 1,0, nullptr, 0);
    ln_add_kernel<<<nLnBlocks, 256>>>(xn, h, t, ln2g, ln2b, M1);

    // ---- FFN ----
    gemm(xn,  W1, big, M1, DF, Dd, 0,0,0, 1,0, b1, 1);   // relu(xn@W1+b1)
    gemm(big, W2, y,   M1, Dd, DF, 0,0,0, 1,0, b2, 0);   // y
    ln_add_kernel<<<nLnBlocks, 256>>>(out1, xn, y, ln3g, ln3b, M1);  // output 1

    // ---- dynamic adjacency A = y@W3 + b3  ([192][512][512] in g_big) ----
    gemm(y, W3, big, M1, Nn, Dd, 0,0,0, 1,0, b3, 0);

    // ---- GCN ----
    transpose_g0_kernel<<<dim3(16,4,BLn), dim3(32,8)>>>(data, Hb);   // g0 -> rows 0..127
    // s1 = g0@S         -> rows 128..255
    gemm(Hb,              support, Hb +  65536, 128, Nn, Nn, 327680LL, 0,        327680LL, BLn, 0, nullptr, 0);
    // d1 = g0@A[bl]     -> rows 384..511
    gemm(Hb,              big,     Hb + 196608, 128, Nn, Nn, 327680LL, 262144LL, 327680LL, BLn, 0, nullptr, 0);
    // s2 = s1@S         -> rows 256..383
    gemm(Hb +  65536,     support, Hb + 131072, 128, Nn, Nn, 327680LL, 0,        327680LL, BLn, 0, nullptr, 0);
    // d2 = d1@A[bl]     -> rows 512..639
    gemm(Hb + 196608,     big,     Hb + 262144, 128, Nn, Nn, 327680LL, 262144LL, 327680LL, BLn, 0, nullptr, 0);
    // gout[bl] = gcn_W[l] @ Hc[bl]   (K = 640)
    gemm(gcnW, Hb, go, 128, Nn, 5*Dd, 81920LL, 327680LL, 65536LL, BLn, Ll, nullptr, 0);
    // dts = gout^T + gcn_b  -> output 2
    transpose_gout_kernel<<<dim3(16,4,BLn), dim3(32,8)>>>(go, gcnB, out2);
}

// round 4
// speedup vs baseline: 1.0004x; 1.0004x over previous
#include <cuda_runtime.h>
#include <cuda_bf16.h>

// Shapes
#define Bb 4
#define Ll 48
#define LP 96
#define Nn 512
#define Dd 128
#define DF 512
#define Hh 8
#define HD 16

#define M1 (Bb*Ll*Nn)    // 98304
#define M2 (Bb*LP*Nn)    // 196608
#define BLn (Bb*Ll)      // 192

// ---------------- scratch (static device memory; no allocations) ----------------
__device__ float g_q [M1*Dd];
__device__ float g_k [M2*Dd];
__device__ float g_v [M2*Dd];
__device__ float g_t [M1*Dd];
__device__ float g_h [M1*Dd];
__device__ float g_xn[M1*Dd];
__device__ float g_y [M1*Dd];
__device__ float g_big[(long long)M1*DF];          // y1 then A
__device__ float g_Hb[(long long)BLn*640*Nn];      // Hc: [192][640][512]
__device__ float g_go[(long long)BLn*Dd*Nn];       // gout: [192][128][512]

__device__ __forceinline__ unsigned f2tf32(float x) {
    unsigned u;
    asm("cvt.rna.tf32.f32 %0, %1;" : "=r"(u) : "f"(x));
    return u;
}

// ---------------- MMA compute phase on one smem buffer ----------------
__device__ __forceinline__ void mma_tile(
    const float (*__restrict__ As)[20], const float (*__restrict__ Bs)[136],
    int wm, int wn, int lr, int lc, float acc[4][4][4])
{
    #pragma unroll
    for (int kk = 0; kk < 16; kk += 8) {
        unsigned a[4][4], b[4][2];
        #pragma unroll
        for (int mf = 0; mf < 4; mf++) {
            int row = wm*64 + mf*16 + lr;
            a[mf][0] = __float_as_uint(As[row  ][kk + lc]);
            a[mf][1] = __float_as_uint(As[row+8][kk + lc]);
            a[mf][2] = __float_as_uint(As[row  ][kk + lc + 4]);
            a[mf][3] = __float_as_uint(As[row+8][kk + lc + 4]);
        }
        #pragma unroll
        for (int nf = 0; nf < 4; nf++) {
            int col = wn*32 + nf*8 + lr;
            b[nf][0] = __float_as_uint(Bs[kk + lc    ][col]);
            b[nf][1] = __float_as_uint(Bs[kk + lc + 4][col]);
        }
        #pragma unroll
        for (int mf = 0; mf < 4; mf++)
            #pragma unroll
            for (int nf = 0; nf < 4; nf++) {
                asm volatile(
                    "mma.sync.aligned.m16n8k8.row.col.f32.tf32.tf32.f32 "
                    "{%0,%1,%2,%3}, {%4,%5,%6,%7}, {%8,%9}, {%0,%1,%2,%3};\n"
                    : "+f"(acc[mf][nf][0]), "+f"(acc[mf][nf][1]),
                      "+f"(acc[mf][nf][2]), "+f"(acc[mf][nf][3])
                    : "r"(a[mf][0]), "r"(a[mf][1]), "r"(a[mf][2]), "r"(a[mf][3]),
                      "r"(b[nf][0]), "r"(b[nf][1]));
            }
    }
}

// ---------------- TF32 tensor-core GEMM, double-buffered: C = A@B (+bias)(+relu) ----------------
// A[M,K] row-major, B[K,N] row-major, C[M,N]. 128x128 tile, k-step 16, 8 warps.
// Per batch z: A += (modA? z%modA : z)*sA ; B += z*sB ; C += z*sC.
__global__ void __launch_bounds__(256) sgemm_kernel(
    const float* __restrict__ A, const float* __restrict__ B, float* __restrict__ C,
    int M, int N, int K,
    long long sA, long long sB, long long sC, int modA,
    const float* __restrict__ bias, int doRelu)
{
    __shared__ float As[2][128][20];
    __shared__ float Bs[2][16][136];

    int z = blockIdx.z;
    const float* Ap = A + (long long)(modA > 0 ? (z % modA) : z) * sA;
    const float* Bp = B + (long long)z * sB;
    float*       Cp = C + (long long)z * sC;

    int tid  = threadIdx.x;
    int warp = tid >> 5;
    int lane = tid & 31;
    int wm = warp >> 2;   // 0..1
    int wn = warp & 3;    // 0..3
    int lr = lane >> 2;   // 0..7
    int lc = lane & 3;    // 0..3

    int brow = blockIdx.y * 128;
    int bcol = blockIdx.x * 128;

    // load maps
    int rA = tid >> 2;           // 0..63  (second load at +64)
    int cA = (tid & 3) * 4;      // 0,4,8,12
    int rB = tid >> 5;           // 0..7   (second load at +8)
    int cB = (tid & 31) * 4;     // 0..124

    const float* aPtr = Ap + (long long)(brow + rA) * K + cA;
    const float* bPtr = Bp + (long long)rB * N + bcol + cB;
    const long long aOff2 = 64LL * K;
    const long long bOff2 = 8LL * N;

    float acc[4][4][4];
    #pragma unroll
    for (int i = 0; i < 4; i++)
        #pragma unroll
        for (int j = 0; j < 4; j++)
            #pragma unroll
            for (int r = 0; r < 4; r++) acc[i][j][r] = 0.f;

    // prologue: tile 0 -> buf 0
    float4 va0 = *(const float4*)aPtr;
    float4 va1 = *(const float4*)(aPtr + aOff2);
    float4 vb0 = *(const float4*)bPtr;
    float4 vb1 = *(const float4*)(bPtr + bOff2);
    aPtr += 16; bPtr += 16LL * N;

    {
        As[0][rA   ][cA+0] = __uint_as_float(f2tf32(va0.x));
        As[0][rA   ][cA+1] = __uint_as_float(f2tf32(va0.y));
        As[0][rA   ][cA+2] = __uint_as_float(f2tf32(va0.z));
        As[0][rA   ][cA+3] = __uint_as_float(f2tf32(va0.w));
        As[0][rA+64][cA+0] = __uint_as_float(f2tf32(va1.x));
        As[0][rA+64][cA+1] = __uint_as_float(f2tf32(va1.y));
        As[0][rA+64][cA+2] = __uint_as_float(f2tf32(va1.z));
        As[0][rA+64][cA+3] = __uint_as_float(f2tf32(va1.w));
        Bs[0][rB  ][cB+0] = __uint_as_float(f2tf32(vb0.x));
        Bs[0][rB  ][cB+1] = __uint_as_float(f2tf32(vb0.y));
        Bs[0][rB  ][cB+2] = __uint_as_float(f2tf32(vb0.z));
        Bs[0][rB  ][cB+3] = __uint_as_float(f2tf32(vb0.w));
        Bs[0][rB+8][cB+0] = __uint_as_float(f2tf32(vb1.x));
        Bs[0][rB+8][cB+1] = __uint_as_float(f2tf32(vb1.y));
        Bs[0][rB+8][cB+2] = __uint_as_float(f2tf32(vb1.z));
        Bs[0][rB+8][cB+3] = __uint_as_float(f2tf32(vb1.w));
    }
    __syncthreads();

    int buf = 0;
    for (int k0 = 16; k0 < K; k0 += 16) {
        // issue next tile's loads early
        va0 = *(const float4*)aPtr;
        va1 = *(const float4*)(aPtr + aOff2);
        vb0 = *(const float4*)bPtr;
        vb1 = *(const float4*)(bPtr + bOff2);
        aPtr += 16; bPtr += 16LL * N;

        // compute current buffer while loads are in flight
        mma_tile(As[buf], Bs[buf], wm, wn, lr, lc, acc);

        // store into alternate buffer
        int nb = buf ^ 1;
        As[nb][rA   ][cA+0] = __uint_as_float(f2tf32(va0.x));
        As[nb][rA   ][cA+1] = __uint_as_float(f2tf32(va0.y));
        As[nb][rA   ][cA+2] = __uint_as_float(f2tf32(va0.z));
        As[nb][rA   ][cA+3] = __uint_as_float(f2tf32(va0.w));
        As[nb][rA+64][cA+0] = __uint_as_float(f2tf32(va1.x));
        As[nb][rA+64][cA+1] = __uint_as_float(f2tf32(va1.y));
        As[nb][rA+64][cA+2] = __uint_as_float(f2tf32(va1.z));
        As[nb][rA+64][cA+3] = __uint_as_float(f2tf32(va1.w));
        Bs[nb][rB  ][cB+0] = __uint_as_float(f2tf32(vb0.x));
        Bs[nb][rB  ][cB+1] = __uint_as_float(f2tf32(vb0.y));
        Bs[nb][rB  ][cB+2] = __uint_as_float(f2tf32(vb0.z));
        Bs[nb][rB  ][cB+3] = __uint_as_float(f2tf32(vb0.w));
        Bs[nb][rB+8][cB+0] = __uint_as_float(f2tf32(vb1.x));
        Bs[nb][rB+8][cB+1] = __uint_as_float(f2tf32(vb1.y));
        Bs[nb][rB+8][cB+2] = __uint_as_float(f2tf32(vb1.z));
        Bs[nb][rB+8][cB+3] = __uint_as_float(f2tf32(vb1.w));
        __syncthreads();
        buf = nb;
    }
    mma_tile(As[buf], Bs[buf], wm, wn, lr, lc, acc);

    // epilogue
    #pragma unroll
    for (int mf = 0; mf < 4; mf++) {
        int row0 = brow + wm*64 + mf*16 + lr;
        #pragma unroll
        for (int nf = 0; nf < 4; nf++) {
            int col = bcol + wn*32 + nf*8 + lc*2;
            float bx = 0.f, by = 0.f;
            if (bias) { bx = bias[col]; by = bias[col+1]; }
            float v0 = acc[mf][nf][0] + bx;
            float v1 = acc[mf][nf][1] + by;
            float v2 = acc[mf][nf][2] + bx;
            float v3 = acc[mf][nf][3] + by;
            if (doRelu) {
                v0 = fmaxf(v0, 0.f); v1 = fmaxf(v1, 0.f);
                v2 = fmaxf(v2, 0.f); v3 = fmaxf(v3, 0.f);
            }
            *(float2*)(Cp + (long long)row0*N + col)     = make_float2(v0, v1);
            *(float2*)(Cp + (long long)(row0+8)*N + col) = make_float2(v2, v3);
        }
    }
}

// ---------------- attention: one block per (b, n, h), 256 threads ----------------
// Q [B,Lq,N,D], K/V [B,Lk,N,D]; head h = cols h*16..h*16+15. Softmax over Lk.
// Scores stored transposed St[m][l] (pad 52) so the AV phase is float4-coalesced.
#define STP 52
__global__ void __launch_bounds__(256) attn_kernel(
    const float* __restrict__ Q, const float* __restrict__ Kt, const float* __restrict__ V,
    float* __restrict__ O, int Lq, int Lk)
{
    __shared__ float Qs[48*20];
    __shared__ float Ks[96*20];
    __shared__ float Vs[96*20];
    __shared__ float St[96*STP];   // [m][l]

    int bid = blockIdx.x;
    int h = bid & 7;
    int n = (bid >> 3) & (Nn - 1);
    int b = bid >> 12;
    int tid = threadIdx.x;

    for (int i = tid; i < Lq*4; i += 256) {
        int l = i >> 2, j4 = i & 3;
        float4 v = *(const float4*)(Q + (((long long)(b*Lq + l))*Nn + n)*Dd + h*HD + j4*4);
        *(float4*)&Qs[l*20 + j4*4] = v;
    }
    for (int i = tid; i < Lk*4; i += 256) {
        int m = i >> 2, j4 = i & 3;
        long long base = (((long long)(b*Lk + m))*Nn + n)*Dd + h*HD + j4*4;
        *(float4*)&Ks[m*20 + j4*4] = *(const float4*)(Kt + base);
        *(float4*)&Vs[m*20 + j4*4] = *(const float4*)(V + base);
    }
    __syncthreads();

    const float scale = 0.25f;  // 1/sqrt(16)

    // QK^T with 2l x 4m register tiling; write transposed scores
    int tlc = Lq >> 1;   // 24
    int tmc = Lk >> 2;   // 12 or 24
    for (int t = tid; t < tlc*tmc; t += 256) {
        int tl = t / tmc, tm = t - tl*tmc;
        int l0 = tl*2, m0 = tm*4;
        const float4* q0 = (const float4*)&Qs[l0*20];
        const float4* q1 = (const float4*)&Qs[(l0+1)*20];
        float4 qa0 = q0[0], qa1 = q0[1], qa2 = q0[2], qa3 = q0[3];
        float4 qb0 = q1[0], qb1 = q1[1], qb2 = q1[2], qb3 = q1[3];
        #pragma unroll
        for (int mi = 0; mi < 4; mi++) {
            const float4* kp = (const float4*)&Ks[(m0+mi)*20];
            float4 k0 = kp[0], k1 = kp[1], k2 = kp[2], k3 = kp[3];
            float sA = 0.f, sB = 0.f;
            sA = fmaf(qa0.x,k0.x,sA); sA = fmaf(qa0.y,k0.y,sA); sA = fmaf(qa0.z,k0.z,sA); sA = fmaf(qa0.w,k0.w,sA);
            sA = fmaf(qa1.x,k1.x,sA); sA = fmaf(qa1.y,k1.y,sA); sA = fmaf(qa1.z,k1.z,sA); sA = fmaf(qa1.w,k1.w,sA);
            sA = fmaf(qa2.x,k2.x,sA); sA = fmaf(qa2.y,k2.y,sA); sA = fmaf(qa2.z,k2.z,sA); sA = fmaf(qa2.w,k2.w,sA);
            sA = fmaf(qa3.x,k3.x,sA); sA = fmaf(qa3.y,k3.y,sA); sA = fmaf(qa3.z,k3.z,sA); sA = fmaf(qa3.w,k3.w,sA);
            sB = fmaf(qb0.x,k0.x,sB); sB = fmaf(qb0.y,k0.y,sB); sB = fmaf(qb0.z,k0.z,sB); sB = fmaf(qb0.w,k0.w,sB);
            sB = fmaf(qb1.x,k1.x,sB); sB = fmaf(qb1.y,k1.y,sB); sB = fmaf(qb1.z,k1.z,sB); sB = fmaf(qb1.w,k1.w,sB);
            sB = fmaf(qb2.x,k2.x,sB); sB = fmaf(qb2.y,k2.y,sB); sB = fmaf(qb2.z,k2.z,sB); sB = fmaf(qb2.w,k2.w,sB);
            sB = fmaf(qb3.x,k3.x,sB); sB = fmaf(qb3.y,k3.y,sB); sB = fmaf(qb3.z,k3.z,sB); sB = fmaf(qb3.w,k3.w,sB);
            St[(m0+mi)*STP + l0]     = sA * scale;
            St[(m0+mi)*STP + l0 + 1] = sB * scale;
        }
    }
    __syncthreads();

    // softmax over m (columns of St) — one thread per l
    if (tid < Lq) {
        float mx = -1e30f;
        for (int m = 0; m < Lk; m++) mx = fmaxf(mx, St[m*STP + tid]);
        float sum = 0.f;
        for (int m = 0; m < Lk; m++) {
            float e = __expf(St[m*STP + tid] - mx);
            St[m*STP + tid] = e;
            sum += e;
        }
        float inv = 1.f / sum;
        for (int m = 0; m < Lk; m++) St[m*STP + tid] *= inv;
    }
    __syncthreads();

    // AV: 4l x j4 tiling — V rows reused across 4 l's; all loads float4
    if (tid < (Lq >> 2) * 4) {
        int lt = tid >> 2, j4 = tid & 3;
        int l0 = lt * 4;
        float4 a0 = make_float4(0,0,0,0), a1 = a0, a2 = a0, a3 = a0;
        #pragma unroll 2
        for (int m = 0; m < Lk; m++) {
            float4 v = *(const float4*)&Vs[m*20 + j4*4];
            float4 s = *(const float4*)&St[m*STP + l0];
            a0.x = fmaf(s.x, v.x, a0.x); a0.y = fmaf(s.x, v.y, a0.y);
            a0.z = fmaf(s.x, v.z, a0.z); a0.w = fmaf(s.x, v.w, a0.w);
            a1.x = fmaf(s.y, v.x, a1.x); a1.y = fmaf(s.y, v.y, a1.y);
            a1.z = fmaf(s.y, v.z, a1.z); a1.w = fmaf(s.y, v.w, a1.w);
            a2.x = fmaf(s.z, v.x, a2.x); a2.y = fmaf(s.z, v.y, a2.y);
            a2.z = fmaf(s.z, v.z, a2.z); a2.w = fmaf(s.z, v.w, a2.w);
            a3.x = fmaf(s.w, v.x, a3.x); a3.y = fmaf(s.w, v.y, a3.y);
            a3.z = fmaf(s.w, v.z, a3.z); a3.w = fmaf(s.w, v.w, a3.w);
        }
        long long ob = (((long long)(b*Lq + l0))*Nn + n)*Dd + h*HD + j4*4;
        const long long rs = (long long)Nn * Dd;
        *(float4*)(O + ob)        = a0;
        *(float4*)(O + ob + rs)   = a1;
        *(float4*)(O + ob + 2*rs) = a2;
        *(float4*)(O + ob + 3*rs) = a3;
    }
}

// ---------------- fused residual add + LayerNorm (1 warp per 128-elem row) ----------------
__global__ void __launch_bounds__(256) ln_add_kernel(
    float* __restrict__ out, const float* __restrict__ X, const float* __restrict__ P,
    const float* __restrict__ g, const float* __restrict__ bta, int rows)
{
    int row  = (blockIdx.x * 256 + threadIdx.x) >> 5;
    int lane = threadIdx.x & 31;
    if (row >= rows) return;
    long long base = (long long)row * Dd + lane*4;
    float4 a = *(const float4*)(X + base);
    float4 p = *(const float4*)(P + base);
    float v0 = a.x+p.x, v1 = a.y+p.y, v2 = a.z+p.z, v3 = a.w+p.w;
    float s  = v0+v1+v2+v3;
    float s2 = v0*v0+v1*v1+v2*v2+v3*v3;
    #pragma unroll
    for (int o = 16; o; o >>= 1) {
        s  += __shfl_xor_sync(0xffffffffu, s,  o);
        s2 += __shfl_xor_sync(0xffffffffu, s2, o);
    }
    float mu  = s * (1.f/128.f);
    float var = s2 * (1.f/128.f) - mu*mu;
    float rs  = rsqrtf(var + 1e-5f);
    float4 gg = *(const float4*)(g   + lane*4);
    float4 bb = *(const float4*)(bta + lane*4);
    float4 o4;
    o4.x = (v0-mu)*rs*gg.x + bb.x;
    o4.y = (v1-mu)*rs*gg.y + bb.y;
    o4.z = (v2-mu)*rs*gg.z + bb.z;
    o4.w = (v3-mu)*rs*gg.w + bb.w;
    *(float4*)(out + base) = o4;
}

// ---------------- transpose data[b,l] ([512,128]) -> g0 rows of Hc ([128,512]) ----------------
__global__ void transpose_g0_kernel(const float* __restrict__ in, float* __restrict__ out)
{
    __shared__ float t[32][33];
    int bl = blockIdx.z;
    int n0 = blockIdx.x * 32;
    int c0 = blockIdx.y * 32;
    const float* ip = in  + (long long)bl * (Nn*Dd);
    float*       op = out + (long long)bl * (640*Nn);
    #pragma unroll
    for (int j = 0; j < 32; j += 8)
        t[threadIdx.y + j][threadIdx.x] = ip[(n0 + threadIdx.y + j)*Dd + c0 + threadIdx.x];
    __syncthreads();
    #pragma unroll
    for (int j = 0; j < 32; j += 8)
        op[(c0 + threadIdx.y + j)*Nn + n0 + threadIdx.x] = t[threadIdx.x][threadIdx.y + j];
}

// ---------------- transpose gout[bl] ([128,512]) + gcn_b -> dts ([512,128]) ----------------
__global__ void transpose_gout_kernel(const float* __restrict__ in, const float* __restrict__ gb,
                                      float* __restrict__ out)
{
    __shared__ float t[32][33];
    int bl = blockIdx.z;
    int l  = bl % Ll;
    int n0 = blockIdx.x * 32;
    int o0 = blockIdx.y * 32;
    const float* ip = in  + (long long)bl * (Dd*Nn);
    float*       op = out + (long long)bl * (Nn*Dd);
    #pragma unroll
    for (int j = 0; j < 32; j += 8)
        t[threadIdx.y + j][threadIdx.x] = ip[(o0 + threadIdx.y + j)*Nn + n0 + threadIdx.x];
    __syncthreads();
    #pragma unroll
    for (int j = 0; j < 32; j += 8) {
        int o = o0 + threadIdx.x;
        op[(n0 + threadIdx.y + j)*Dd + o] = t[threadIdx.x][threadIdx.y + j] + gb[l*Dd + o];
    }
}

// ---------------- host ----------------
static inline void gemm(const float* A, const float* B, float* C, int M, int N, int K,
                        long long sA, long long sB, long long sC, int batch, int modA,
                        const float* bias, int relu)
{
    dim3 grid(N/128, M/128, batch);
    sgemm_kernel<<<grid, 256>>>(A, B, C, M, N, K, sA, sB, sC, modA, bias, relu);
}

extern "C" void kernel_launch(void* const* d_in, const int* in_sizes, int n_in,
                              void* d_out, int out_size)
{
    const float* x       = (const float*)d_in[0];
    const float* memory  = (const float*)d_in[1];
    const float* data    = (const float*)d_in[2];
    const float* support = (const float*)d_in[3];
    const float* Wq_s = (const float*)d_in[4];
    const float* Wk_s = (const float*)d_in[5];
    const float* Wv_s = (const float*)d_in[6];
    const float* Wo_s = (const float*)d_in[7];
    const float* Wq_c = (const float*)d_in[8];
    const float* Wk_c = (const float*)d_in[9];
    const float* Wv_c = (const float*)d_in[10];
    const float* Wo_c = (const float*)d_in[11];
    const float* W1   = (const float*)d_in[12];
    const float* b1   = (const float*)d_in[13];
    const float* W2   = (const float*)d_in[14];
    const float* b2   = (const float*)d_in[15];
    const float* W3   = (const float*)d_in[16];
    const float* b3   = (const float*)d_in[17];
    const float* gcnW = (const float*)d_in[18];
    const float* gcnB = (const float*)d_in[19];
    const float* ln1g = (const float*)d_in[20];
    const float* ln1b = (const float*)d_in[21];
    const float* ln2g = (const float*)d_in[22];
    const float* ln2b = (const float*)d_in[23];
    const float* ln3g = (const float*)d_in[24];
    const float* ln3b = (const float*)d_in[25];

    float *q, *k, *v, *t, *h, *xn, *y, *big, *Hb, *go;
    cudaGetSymbolAddress((void**)&q,  g_q);
    cudaGetSymbolAddress((void**)&k,  g_k);
    cudaGetSymbolAddress((void**)&v,  g_v);
    cudaGetSymbolAddress((void**)&t,  g_t);
    cudaGetSymbolAddress((void**)&h,  g_h);
    cudaGetSymbolAddress((void**)&xn, g_xn);
    cudaGetSymbolAddress((void**)&y,  g_y);
    cudaGetSymbolAddress((void**)&big, g_big);
    cudaGetSymbolAddress((void**)&Hb, g_Hb);
    cudaGetSymbolAddress((void**)&go, g_go);

    float* out1 = (float*)d_out;               // LN3(xn + y)
    float* out2 = out1 + (long long)M1 * Dd;   // dts

    const int nLnBlocks = M1 / 8;              // 8 rows per 256-thr block

    // ---- self-attention ----
    gemm(x, Wq_s, q, M1, Dd, Dd, 0,0,0, 1,0, nullptr, 0);
    gemm(x, Wk_s, k, M1, Dd, Dd, 0,0,0, 1,0, nullptr, 0);
    gemm(x, Wv_s, v, M1, Dd, Dd, 0,0,0, 1,0, nullptr, 0);
    attn_kernel<<<Bb*Nn*Hh, 256>>>(q, k, v, t, Ll, Ll);
    gemm(t, Wo_s, q, M1, Dd, Dd, 0,0,0, 1,0, nullptr, 0);
    ln_add_kernel<<<nLnBlocks, 256>>>(h, x, q, ln1g, ln1b, M1);

    // ---- cross-attention ----
    gemm(h,      Wq_c, t, M1, Dd, Dd, 0,0,0, 1,0, nullptr, 0);
    gemm(memory, Wk_c, k, M2, Dd, Dd, 0,0,0, 1,0, nullptr, 0);
    gemm(memory, Wv_c, v, M2, Dd, Dd, 0,0,0, 1,0, nullptr, 0);
    attn_kernel<<<Bb*Nn*Hh, 256>>>(t, k, v, q, Ll, LP);
    gemm(q, Wo_c, t, M1, Dd, Dd, 0,0,0, 1,0, nullptr, 0);
    ln_add_kernel<<<nLnBlocks, 256>>>(xn, h, t, ln2g, ln2b, M1);

    // ---- FFN ----
    gemm(xn,  W1, big, M1, DF, Dd, 0,0,0, 1,0, b1, 1);   // relu(xn@W1+b1)
    gemm(big, W2, y,   M1, Dd, DF, 0,0,0, 1,0, b2, 0);   // y
    ln_add_kernel<<<nLnBlocks, 256>>>(out1, xn, y, ln3g, ln3b, M1);  // output 1

    // ---- dynamic adjacency A = y@W3 + b3  ([192][512][512] in g_big) ----
    gemm(y, W3, big, M1, Nn, Dd, 0,0,0, 1,0, b3, 0);

    // ---- GCN ----
    transpose_g0_kernel<<<dim3(16,4,BLn), dim3(32,8)>>>(data, Hb);   // g0 -> rows 0..127
    // s1 = g0@S         -> rows 128..255
    gemm(Hb,              support, Hb +  65536, 128, Nn, Nn, 327680LL, 0,        327680LL, BLn, 0, nullptr, 0);
    // d1 = g0@A[bl]     -> rows 384..511
    gemm(Hb,              big,     Hb + 196608, 128, Nn, Nn, 327680LL, 262144LL, 327680LL, BLn, 0, nullptr, 0);
    // s2 = s1@S         -> rows 256..383
    gemm(Hb +  65536,     support, Hb + 131072, 128, Nn, Nn, 327680LL, 0,        327680LL, BLn, 0, nullptr, 0);
    // d2 = d1@A[bl]     -> rows 512..639
    gemm(Hb + 196608,     big,     Hb + 262144, 128, Nn, Nn, 327680LL, 262144LL, 327680LL, BLn, 0, nullptr, 0);
    // gout[bl] = gcn_W[l] @ Hc[bl]   (K = 640)
    gemm(gcnW, Hb, go, 128, Nn, 5*Dd, 81920LL, 327680LL, 65536LL, BLn, Ll, nullptr, 0);
    // dts = gout^T + gcn_b  -> output 2
    transpose_gout_kernel<<<dim3(16,4,BLn), dim3(32,8)>>>(go, gcnB, out2);
}

// round 7
// speedup vs baseline: 1.3273x; 1.3268x over previous
#include <cuda_runtime.h>
#include <cuda_fp16.h>
#include <cstdint>

// Shapes
#define Bb 4
#define Ll 48
#define LP 96
#define Nn 512
#define Dd 128
#define DF 512
#define Hh 8
#define HD 16

#define M1 (Bb*Ll*Nn)    // 98304
#define M2 (Bb*LP*Nn)    // 196608
#define BLn (Bb*Ll)      // 192

// ---------------- scratch (static device memory; no allocations) ----------------
__device__ float g_q [M1*Dd];
__device__ float g_k [M2*Dd];
__device__ float g_v [M2*Dd];
__device__ float g_t [M1*Dd];
__device__ float g_h [M1*Dd];
__device__ float g_xn[M1*Dd];
__device__ float g_y [M1*Dd];
__device__ float g_big[(long long)M1*DF];          // y1 then A
__device__ float g_Hb[(long long)BLn*640*Nn];      // Hc: [192][640][512]
__device__ float g_go[(long long)BLn*Dd*Nn];       // gout: [192][128][512]

__device__ __forceinline__ uint32_t h2u(__half2 h) {
    uint32_t u;
    memcpy(&u, &h, 4);
    return u;
}

// ---------------- FP16 tensor-core GEMM: C = A@B (+bias)(+relu), batched ----------------
// A[M,K] row-major, B[K,N] row-major, C[M,N]. 128x128 tile, k-step 32, 8 warps.
// fp32 accumulate; inputs rounded to fp16 (10-bit mantissa, same as tf32).
// Per batch z: A += (modA? z%modA : z)*sA ; B += z*sB ; C += z*sC.
__global__ void __launch_bounds__(256) hgemm_kernel(
    const float* __restrict__ A, const float* __restrict__ B, float* __restrict__ C,
    int M, int N, int K,
    long long sA, long long sB, long long sC, int modA,
    const float* __restrict__ bias, int doRelu)
{
    __shared__ uint32_t As2[128][18];   // half2 bits [m][k/2], 16 used, pad 18
    __shared__ uint32_t Bs2[128][18];   // half2 bits [n][k/2], col-major fragments

    int z = blockIdx.z;
    const float* Ap = A + (long long)(modA > 0 ? (z % modA) : z) * sA;
    const float* Bp = B + (long long)z * sB;
    float*       Cp = C + (long long)z * sC;

    int tid  = threadIdx.x;
    int warp = tid >> 5;
    int lane = tid & 31;
    int wm = warp >> 2;   // 0..1  (64-row warp tile)
    int wn = warp & 3;    // 0..3  (32-col warp tile)
    int lr = lane >> 2;   // 0..7  (groupID)
    int lc = lane & 3;    // 0..3  (threadID in group)

    int brow = blockIdx.y * 128;
    int bcol = blockIdx.x * 128;

    // A load map: 8 threads per row cover 32 k; 32 rows per pass, 4 passes
    int rA = tid >> 3;            // 0..31
    int cA = (tid & 7) * 4;       // 0,4,...,28  (floats)
    // B load map: 128 threads per k-quad; 2 k-quads per pass, 4 passes
    int nB = tid & 127;           // 0..127
    int kqB = tid >> 7;           // 0..1

    float acc[4][4][4];
    #pragma unroll
    for (int i = 0; i < 4; i++)
        #pragma unroll
        for (int j = 0; j < 4; j++)
            #pragma unroll
            for (int r = 0; r < 4; r++) acc[i][j][r] = 0.f;

    for (int k0 = 0; k0 < K; k0 += 32) {
        // ---- stage A tile 128x32 as half2 bits [m][k/2] ----
        #pragma unroll
        for (int u = 0; u < 4; u++) {
            int r = rA + u * 32;
            float4 va = *(const float4*)(Ap + (long long)(brow + r) * K + k0 + cA);
            uint2 pk = make_uint2(h2u(__floats2half2_rn(va.x, va.y)),
                                  h2u(__floats2half2_rn(va.z, va.w)));
            *(uint2*)&As2[r][cA >> 1] = pk;
        }
        // ---- stage B tile 32x128 as half2 bits [n][k/2] (transpose during STS) ----
        #pragma unroll
        for (int u = 0; u < 4; u++) {
            int kq = kqB + u * 2;          // 0..7
            int kk = k0 + kq * 4;
            const float* bp = Bp + (long long)kk * N + bcol + nB;
            float f0 = bp[0];
            float f1 = bp[N];
            float f2 = bp[2*N];
            float f3 = bp[3*N];
            uint2 pk = make_uint2(h2u(__floats2half2_rn(f0, f1)),
                                  h2u(__floats2half2_rn(f2, f3)));
            *(uint2*)&Bs2[nB][kq << 1] = pk;
        }
        __syncthreads();

        // ---- two m16n8k16 k-halves ----
        #pragma unroll
        for (int kk = 0; kk < 2; kk++) {
            int kb = kk * 8;
            uint32_t a[4][4], b[4][2];
            #pragma unroll
            for (int mf = 0; mf < 4; mf++) {
                int row = wm*64 + mf*16 + lr;
                a[mf][0] = As2[row  ][kb + lc];
                a[mf][1] = As2[row+8][kb + lc];
                a[mf][2] = As2[row  ][kb + lc + 4];
                a[mf][3] = As2[row+8][kb + lc + 4];
            }
            #pragma unroll
            for (int nf = 0; nf < 4; nf++) {
                int col = wn*32 + nf*8 + lr;
                b[nf][0] = Bs2[col][kb + lc];
                b[nf][1] = Bs2[col][kb + lc + 4];
            }
            #pragma unroll
            for (int mf = 0; mf < 4; mf++)
                #pragma unroll
                for (int nf = 0; nf < 4; nf++) {
                    asm volatile(
                        "mma.sync.aligned.m16n8k16.row.col.f32.f16.f16.f32 "
                        "{%0,%1,%2,%3}, {%4,%5,%6,%7}, {%8,%9}, {%0,%1,%2,%3};\n"
                        : "+f"(acc[mf][nf][0]), "+f"(acc[mf][nf][1]),
                          "+f"(acc[mf][nf][2]), "+f"(acc[mf][nf][3])
                        : "r"(a[mf][0]), "r"(a[mf][1]), "r"(a[mf][2]), "r"(a[mf][3]),
                          "r"(b[nf][0]), "r"(b[nf][1]));
                }
        }
        __syncthreads();
    }

    // epilogue
    #pragma unroll
    for (int mf = 0; mf < 4; mf++) {
        int row0 = brow + wm*64 + mf*16 + lr;
        #pragma unroll
        for (int nf = 0; nf < 4; nf++) {
            int col = bcol + wn*32 + nf*8 + lc*2;
            float bx = 0.f, by = 0.f;
            if (bias) { bx = bias[col]; by = bias[col+1]; }
            float v0 = acc[mf][nf][0] + bx;
            float v1 = acc[mf][nf][1] + by;
            float v2 = acc[mf][nf][2] + bx;
            float v3 = acc[mf][nf][3] + by;
            if (doRelu) {
                v0 = fmaxf(v0, 0.f); v1 = fmaxf(v1, 0.f);
                v2 = fmaxf(v2, 0.f); v3 = fmaxf(v3, 0.f);
            }
            *(float2*)(Cp + (long long)row0*N + col)     = make_float2(v0, v1);
            *(float2*)(Cp + (long long)(row0+8)*N + col) = make_float2(v2, v3);
        }
    }
}

// ---------------- attention: one block per (b, n, h), 256 threads (R3 proven) ----------------
#define STP 52
__global__ void __launch_bounds__(256) attn_kernel(
    const float* __restrict__ Q, const float* __restrict__ Kt, const float* __restrict__ V,
    float* __restrict__ O, int Lq, int Lk)
{
    __shared__ float Qs[48*20];
    __shared__ float Ks[96*20];
    __shared__ float Vs[96*20];
    __shared__ float St[96*STP];   // [m][l]

    int bid = blockIdx.x;
    int h = bid & 7;
    int n = (bid >> 3) & (Nn - 1);
    int b = bid >> 12;
    int tid = threadIdx.x;

    for (int i = tid; i < Lq*4; i += 256) {
        int l = i >> 2, j4 = i & 3;
        *(float4*)&Qs[l*20 + j4*4] =
            *(const float4*)(Q + (((long long)(b*Lq + l))*Nn + n)*Dd + h*HD + j4*4);
    }
    for (int i = tid; i < Lk*4; i += 256) {
        int m = i >> 2, j4 = i & 3;
        long long base = (((long long)(b*Lk + m))*Nn + n)*Dd + h*HD + j4*4;
        *(float4*)&Ks[m*20 + j4*4] = *(const float4*)(Kt + base);
        *(float4*)&Vs[m*20 + j4*4] = *(const float4*)(V + base);
    }
    __syncthreads();

    const float scale = 0.25f;  // 1/sqrt(16)
    int tlc = Lq >> 1, tmc = Lk >> 2;
    for (int t = tid; t < tlc*tmc; t += 256) {
        int tl = t / tmc, tm = t - tl*tmc;
        int l0 = tl*2, m0 = tm*4;
        const float4* q0 = (const float4*)&Qs[l0*20];
        const float4* q1 = (const float4*)&Qs[(l0+1)*20];
        float4 qa0 = q0[0], qa1 = q0[1], qa2 = q0[2], qa3 = q0[3];
        float4 qb0 = q1[0], qb1 = q1[1], qb2 = q1[2], qb3 = q1[3];
        #pragma unroll
        for (int mi = 0; mi < 4; mi++) {
            const float4* kp = (const float4*)&Ks[(m0+mi)*20];
            float4 k0 = kp[0], k1 = kp[1], k2 = kp[2], k3 = kp[3];
            float sA = 0.f, sB = 0.f;
            sA = fmaf(qa0.x,k0.x,sA); sA = fmaf(qa0.y,k0.y,sA); sA = fmaf(qa0.z,k0.z,sA); sA = fmaf(qa0.w,k0.w,sA);
            sA = fmaf(qa1.x,k1.x,sA); sA = fmaf(qa1.y,k1.y,sA); sA = fmaf(qa1.z,k1.z,sA); sA = fmaf(qa1.w,k1.w,sA);
            sA = fmaf(qa2.x,k2.x,sA); sA = fmaf(qa2.y,k2.y,sA); sA = fmaf(qa2.z,k2.z,sA); sA = fmaf(qa2.w,k2.w,sA);
            sA = fmaf(qa3.x,k3.x,sA); sA = fmaf(qa3.y,k3.y,sA); sA = fmaf(qa3.z,k3.z,sA); sA = fmaf(qa3.w,k3.w,sA);
            sB = fmaf(qb0.x,k0.x,sB); sB = fmaf(qb0.y,k0.y,sB); sB = fmaf(qb0.z,k0.z,sB); sB = fmaf(qb0.w,k0.w,sB);
            sB = fmaf(qb1.x,k1.x,sB); sB = fmaf(qb1.y,k1.y,sB); sB = fmaf(qb1.z,k1.z,sB); sB = fmaf(qb1.w,k1.w,sB);
            sB = fmaf(qb2.x,k2.x,sB); sB = fmaf(qb2.y,k2.y,sB); sB = fmaf(qb2.z,k2.z,sB); sB = fmaf(qb2.w,k2.w,sB);
            sB = fmaf(qb3.x,k3.x,sB); sB = fmaf(qb3.y,k3.y,sB); sB = fmaf(qb3.z,k3.z,sB); sB = fmaf(qb3.w,k3.w,sB);
            St[(m0+mi)*STP + l0]     = sA * scale;
            St[(m0+mi)*STP + l0 + 1] = sB * scale;
        }
    }
    __syncthreads();

    if (tid < Lq) {
        float mx = -1e30f;
        for (int m = 0; m < Lk; m++) mx = fmaxf(mx, St[m*STP + tid]);
        float sum = 0.f;
        for (int m = 0; m < Lk; m++) {
            float e = __expf(St[m*STP + tid] - mx);
            St[m*STP + tid] = e;
            sum += e;
        }
        float inv = 1.f / sum;
        for (int m = 0; m < Lk; m++) St[m*STP + tid] *= inv;
    }
    __syncthreads();

    if (tid < (Lq >> 2) * 4) {
        int lt = tid >> 2, j4 = tid & 3;
        int l0 = lt * 4;
        float4 a0 = make_float4(0,0,0,0), a1 = a0, a2 = a0, a3 = a0;
        #pragma unroll 2
        for (int m = 0; m < Lk; m++) {
            float4 v = *(const float4*)&Vs[m*20 + j4*4];
            float4 s = *(const float4*)&St[m*STP + l0];
            a0.x = fmaf(s.x, v.x, a0.x); a0.y = fmaf(s.x, v.y, a0.y);
            a0.z = fmaf(s.x, v.z, a0.z); a0.w = fmaf(s.x, v.w, a0.w);
            a1.x = fmaf(s.y, v.x, a1.x); a1.y = fmaf(s.y, v.y, a1.y);
            a1.z = fmaf(s.y, v.z, a1.z); a1.w = fmaf(s.y, v.w, a1.w);
            a2.x = fmaf(s.z, v.x, a2.x); a2.y = fmaf(s.z, v.y, a2.y);
            a2.z = fmaf(s.z, v.z, a2.z); a2.w = fmaf(s.z, v.w, a2.w);
            a3.x = fmaf(s.w, v.x, a3.x); a3.y = fmaf(s.w, v.y, a3.y);
            a3.z = fmaf(s.w, v.z, a3.z); a3.w = fmaf(s.w, v.w, a3.w);
        }
        long long ob = (((long long)(b*Lq + l0))*Nn + n)*Dd + h*HD + j4*4;
        const long long rs = (long long)Nn * Dd;
        *(float4*)(O + ob)        = a0;
        *(float4*)(O + ob + rs)   = a1;
        *(float4*)(O + ob + 2*rs) = a2;
        *(float4*)(O + ob + 3*rs) = a3;
    }
}

// ---------------- fused residual add + LayerNorm ----------------
__global__ void __launch_bounds__(256) ln_add_kernel(
    float* __restrict__ out, const float* __restrict__ X, const float* __restrict__ P,
    const float* __restrict__ g, const float* __restrict__ bta, int rows)
{
    int row  = (blockIdx.x * 256 + threadIdx.x) >> 5;
    int lane = threadIdx.x & 31;
    if (row >= rows) return;
    long long base = (long long)row * Dd + lane*4;
    float4 a = *(const float4*)(X + base);
    float4 p = *(const float4*)(P + base);
    float v0 = a.x+p.x, v1 = a.y+p.y, v2 = a.z+p.z, v3 = a.w+p.w;
    float s  = v0+v1+v2+v3;
    float s2 = v0*v0+v1*v1+v2*v2+v3*v3;
    #pragma unroll
    for (int o = 16; o; o >>= 1) {
        s  += __shfl_xor_sync(0xffffffffu, s,  o);
        s2 += __shfl_xor_sync(0xffffffffu, s2, o);
    }
    float mu  = s * (1.f/128.f);
    float var = s2 * (1.f/128.f) - mu*mu;
    float rs  = rsqrtf(var + 1e-5f);
    float4 gg = *(const float4*)(g   + lane*4);
    float4 bb = *(const float4*)(bta + lane*4);
    float4 o4;
    o4.x = (v0-mu)*rs*gg.x + bb.x;
    o4.y = (v1-mu)*rs*gg.y + bb.y;
    o4.z = (v2-mu)*rs*gg.z + bb.z;
    o4.w = (v3-mu)*rs*gg.w + bb.w;
    *(float4*)(out + base) = o4;
}

// ---------------- transpose data[b,l] ([512,128]) -> g0 rows of Hc ([128,512]) ----------------
__global__ void transpose_g0_kernel(const float* __restrict__ in, float* __restrict__ out)
{
    __shared__ float t[32][33];
    int bl = blockIdx.z;
    int n0 = blockIdx.x * 32;
    int c0 = blockIdx.y * 32;
    const float* ip = in  + (long long)bl * (Nn*Dd);
    float*       op = out + (long long)bl * (640*Nn);
    #pragma unroll
    for (int j = 0; j < 32; j += 8)
        t[threadIdx.y + j][threadIdx.x] = ip[(n0 + threadIdx.y + j)*Dd + c0 + threadIdx.x];
    __syncthreads();
    #pragma unroll
    for (int j = 0; j < 32; j += 8)
        op[(c0 + threadIdx.y + j)*Nn + n0 + threadIdx.x] = t[threadIdx.x][threadIdx.y + j];
}

// ---------------- transpose gout[bl] ([128,512]) + gcn_b -> dts ([512,128]) ----------------
__global__ void transpose_gout_kernel(const float* __restrict__ in, const float* __restrict__ gb,
                                      float* __restrict__ out)
{
    __shared__ float t[32][33];
    int bl = blockIdx.z;
    int l  = bl % Ll;
    int n0 = blockIdx.x * 32;
    int o0 = blockIdx.y * 32;
    const float* ip = in  + (long long)bl * (Dd*Nn);
    float*       op = out + (long long)bl * (Nn*Dd);
    #pragma unroll
    for (int j = 0; j < 32; j += 8)
        t[threadIdx.y + j][threadIdx.x] = ip[(o0 + threadIdx.y + j)*Nn + n0 + threadIdx.x];
    __syncthreads();
    #pragma unroll
    for (int j = 0; j < 32; j += 8) {
        int o = o0 + threadIdx.x;
        op[(n0 + threadIdx.y + j)*Dd + o] = t[threadIdx.x][threadIdx.y + j] + gb[l*Dd + o];
    }
}

// ---------------- host ----------------
static inline void gemm(const float* A, const float* B, float* C, int M, int N, int K,
                        long long sA, long long sB, long long sC, int batch, int modA,
                        const float* bias, int relu)
{
    dim3 grid(N/128, M/128, batch);
    hgemm_kernel<<<grid, 256>>>(A, B, C, M, N, K, sA, sB, sC, modA, bias, relu);
}

extern "C" void kernel_launch(void* const* d_in, const int* in_sizes, int n_in,
                              void* d_out, int out_size)
{
    const float* x       = (const float*)d_in[0];
    const float* memory  = (const float*)d_in[1];
    const float* data    = (const float*)d_in[2];
    const float* support = (const float*)d_in[3];
    const float* Wq_s = (const float*)d_in[4];
    const float* Wk_s = (const float*)d_in[5];
    const float* Wv_s = (const float*)d_in[6];
    const float* Wo_s = (const float*)d_in[7];
    const float* Wq_c = (const float*)d_in[8];
    const float* Wk_c = (const float*)d_in[9];
    const float* Wv_c = (const float*)d_in[10];
    const float* Wo_c = (const float*)d_in[11];
    const float* W1   = (const float*)d_in[12];
    const float* b1   = (const float*)d_in[13];
    const float* W2   = (const float*)d_in[14];
    const float* b2   = (const float*)d_in[15];
    const float* W3   = (const float*)d_in[16];
    const float* b3   = (const float*)d_in[17];
    const float* gcnW = (const float*)d_in[18];
    const float* gcnB = (const float*)d_in[19];
    const float* ln1g = (const float*)d_in[20];
    const float* ln1b = (const float*)d_in[21];
    const float* ln2g = (const float*)d_in[22];
    const float* ln2b = (const float*)d_in[23];
    const float* ln3g = (const float*)d_in[24];
    const float* ln3b = (const float*)d_in[25];

    float *q, *k, *v, *t, *h, *xn, *y, *big, *Hb, *go;
    cudaGetSymbolAddress((void**)&q,  g_q);
    cudaGetSymbolAddress((void**)&k,  g_k);
    cudaGetSymbolAddress((void**)&v,  g_v);
    cudaGetSymbolAddress((void**)&t,  g_t);
    cudaGetSymbolAddress((void**)&h,  g_h);
    cudaGetSymbolAddress((void**)&xn, g_xn);
    cudaGetSymbolAddress((void**)&y,  g_y);
    cudaGetSymbolAddress((void**)&big, g_big);
    cudaGetSymbolAddress((void**)&Hb, g_Hb);
    cudaGetSymbolAddress((void**)&go, g_go);

    float* out1 = (float*)d_out;               // LN3(xn + y)
    float* out2 = out1 + (long long)M1 * Dd;   // dts

    const int nLnBlocks = M1 / 8;

    // ---- self-attention ----
    gemm(x, Wq_s, q, M1, Dd, Dd, 0,0,0, 1,0, nullptr, 0);
    gemm(x, Wk_s, k, M1, Dd, Dd, 0,0,0, 1,0, nullptr, 0);
    gemm(x, Wv_s, v, M1, Dd, Dd, 0,0,0, 1,0, nullptr, 0);
    attn_kernel<<<Bb*Nn*Hh, 256>>>(q, k, v, t, Ll, Ll);
    gemm(t, Wo_s, q, M1, Dd, Dd, 0,0,0, 1,0, nullptr, 0);
    ln_add_kernel<<<nLnBlocks, 256>>>(h, x, q, ln1g, ln1b, M1);

    // ---- cross-attention ----
    gemm(h,      Wq_c, t, M1, Dd, Dd, 0,0,0, 1,0, nullptr, 0);
    gemm(memory, Wk_c, k, M2, Dd, Dd, 0,0,0, 1,0, nullptr, 0);
    gemm(memory, Wv_c, v, M2, Dd, Dd, 0,0,0, 1,0, nullptr, 0);
    attn_kernel<<<Bb*Nn*Hh, 256>>>(t, k, v, q, Ll, LP);
    gemm(q, Wo_c, t, M1, Dd, Dd, 0,0,0, 1,0, nullptr, 0);
    ln_add_kernel<<<nLnBlocks, 256>>>(xn, h, t, ln2g, ln2b, M1);

    // ---- FFN ----
    gemm(xn,  W1, big, M1, DF, Dd, 0,0,0, 1,0, b1, 1);
    gemm(big, W2, y,   M1, Dd, DF, 0,0,0, 1,0, b2, 0);
    ln_add_kernel<<<nLnBlocks, 256>>>(out1, xn, y, ln3g, ln3b, M1);

    // ---- dynamic adjacency A = y@W3 + b3 ----
    gemm(y, W3, big, M1, Nn, Dd, 0,0,0, 1,0, b3, 0);

    // ---- GCN ----
    transpose_g0_kernel<<<dim3(16,4,BLn), dim3(32,8)>>>(data, Hb);
    gemm(Hb,          support, Hb +  65536, 128, Nn, Nn, 327680LL, 0,        327680LL, BLn, 0, nullptr, 0);
    gemm(Hb,          big,     Hb + 196608, 128, Nn, Nn, 327680LL, 262144LL, 327680LL, BLn, 0, nullptr, 0);
    gemm(Hb +  65536, support, Hb + 131072, 128, Nn, Nn, 327680LL, 0,        327680LL, BLn, 0, nullptr, 0);
    gemm(Hb + 196608, big,     Hb + 262144, 128, Nn, Nn, 327680LL, 262144LL, 327680LL, BLn, 0, nullptr, 0);
    gemm(gcnW, Hb, go, 128, Nn, 5*Dd, 81920LL, 327680LL, 65536LL, BLn, Ll, nullptr, 0);
    transpose_gout_kernel<<<dim3(16,4,BLn), dim3(32,8)>>>(go, gcnB, out2);
}